// round 4
// baseline (speedup 1.0000x reference)
#include <cuda_runtime.h>
#include <cuda_bf16.h>
#include <cstdint>

#define NTOK 16384
#define MD   2048
#define PD   256
#define NE   64

// ---------------- device globals (no allocation allowed) ----------------
__device__ float g_h[NTOK * PD];                  // 16.8 MB
__device__ __align__(16) __nv_bfloat16 g_Whi[PD * MD];
__device__ __align__(16) __nv_bfloat16 g_Wlo[PD * MD];
__device__ float g_simnT[NE * PD];                // transposed col-normalized sim
__device__ float g_scale;
__device__ float g_active;

// ---------------- prep: split W into bf16 hi/lo ----------------
__global__ void convert_w_kernel(const float* __restrict__ W) {
    int base = blockIdx.x * 2048 + threadIdx.x;
    #pragma unroll
    for (int i = 0; i < 8; i++) {
        int e = base + i * 256;
        float v = W[e];
        __nv_bfloat16 h = __float2bfloat16(v);
        g_Whi[e] = h;
        g_Wlo[e] = __float2bfloat16(v - __bfloat162float(h));
    }
}

// ---------------- prep: sim col-normalize (transposed), scale, active ----------------
__global__ void prep_kernel(const float* __restrict__ sim,
                            const float* __restrict__ temperature,
                            const float* __restrict__ mask) {
    int t = threadIdx.x;
    if (t < NE) {
        float ss = 0.f;
        #pragma unroll 8
        for (int p = 0; p < PD; p++) {
            float v = sim[p * NE + t];
            ss += v * v;
        }
        float inv = 1.f / fmaxf(sqrtf(ss), 1e-12f);
        #pragma unroll 8
        for (int p = 0; p < PD; p++)
            g_simnT[t * PD + p] = sim[p * NE + t] * inv;
    }
    if (t == 0) {
        float a = 0.f;
        for (int e = 0; e < NE; e++) a += mask[e];
        g_active = a;
        g_scale = expf(fminf(temperature[0], 4.6051701859880913680f));
    }
}

// ---------------- GEMM1: h = x @ W^T + b via mma.sync bf16 split ----------------
// Block 128x128, BK=32. 8 warps: warpM = wid&3 (32 rows), warpN = wid>>2 (64 cols).
#define BK 32
#define ASTRIDE 40   // bf16 elems per smem row (80 bytes)

__device__ __forceinline__ uint32_t smem_u32(const void* p) {
    uint32_t a;
    asm("{ .reg .u64 t; cvta.to.shared.u64 t, %1; cvt.u32.u64 %0, t; }" : "=r"(a) : "l"(p));
    return a;
}

#define LDSM4(r0, r1, r2, r3, a)                                                  \
    asm volatile("ldmatrix.sync.aligned.m8n8.x4.shared.b16 {%0,%1,%2,%3}, [%4];" \
                 : "=r"(r0), "=r"(r1), "=r"(r2), "=r"(r3) : "r"(a))

#define MMA16816(c, a, b)                                                         \
    asm volatile("mma.sync.aligned.m16n8k16.row.col.f32.bf16.bf16.f32 "           \
                 "{%0,%1,%2,%3}, {%4,%5,%6,%7}, {%8,%9}, {%0,%1,%2,%3};"          \
                 : "+f"((c)[0]), "+f"((c)[1]), "+f"((c)[2]), "+f"((c)[3])         \
                 : "r"((a)[0]), "r"((a)[1]), "r"((a)[2]), "r"((a)[3]),            \
                   "r"((b)[0]), "r"((b)[1]))

__global__ void __launch_bounds__(256)
mma_gemm1_kernel(const float* __restrict__ X, const float* __restrict__ bias) {
    __shared__ __nv_bfloat16 sAhi[128 * ASTRIDE];
    __shared__ __nv_bfloat16 sAlo[128 * ASTRIDE];
    __shared__ __nv_bfloat16 sBhi[128 * ASTRIDE];
    __shared__ __nv_bfloat16 sBlo[128 * ASTRIDE];

    const int tid = threadIdx.x;
    const int wid = tid >> 5, lane = tid & 31;
    const int warpM = wid & 3, warpN = wid >> 2;
    const int bx = blockIdx.x;   // n tile 0..1
    const int by = blockIdx.y;   // m tile 0..127

    const uint32_t aHb = smem_u32(sAhi), aLb = smem_u32(sAlo);
    const uint32_t bHb = smem_u32(sBhi), bLb = smem_u32(sBlo);

    float acc[2][8][4];
    #pragma unroll
    for (int i = 0; i < 2; i++)
        #pragma unroll
        for (int j = 0; j < 8; j++)
            #pragma unroll
            for (int q = 0; q < 4; q++) acc[i][j][q] = 0.f;

    // ldmatrix source addresses (byte offsets within 80B-stride tiles)
    // A: row = mt*16 + (lane&15), byte = ks*32 + (lane>>4)*16
    const uint32_t aRow = (uint32_t)(lane & 15);
    const uint32_t aByte = (uint32_t)((lane >> 4) * 16);
    // B: g=lane>>3: n = nf2*16 + (g>=2)*8 + (lane&7), byte = (g&1)*16 + ks*32
    const int g = lane >> 3;
    const uint32_t bRow = (uint32_t)(warpN * 64 + ((g >> 1) << 3) + (lane & 7));
    const uint32_t bByte = (uint32_t)((g & 1) * 16);

    for (int k0 = 0; k0 < MD; k0 += BK) {
        __syncthreads();
        // ---- load A tile: X[128 x 32] f32 -> bf16 hi/lo
        #pragma unroll
        for (int i = 0; i < 4; i++) {
            int idx = i * 256 + tid;
            int row = idx >> 3, c4 = (idx & 7) * 4;
            float4 v = *(const float4*)(X + (size_t)(by * 128 + row) * MD + k0 + c4);
            __nv_bfloat16 h0 = __float2bfloat16(v.x), h1 = __float2bfloat16(v.y);
            __nv_bfloat16 h2 = __float2bfloat16(v.z), h3 = __float2bfloat16(v.w);
            float l0 = v.x - __bfloat162float(h0), l1 = v.y - __bfloat162float(h1);
            float l2 = v.z - __bfloat162float(h2), l3 = v.w - __bfloat162float(h3);
            uint32_t ph0 = (uint32_t)__bfloat16_as_ushort(h0) | ((uint32_t)__bfloat16_as_ushort(h1) << 16);
            uint32_t ph1 = (uint32_t)__bfloat16_as_ushort(h2) | ((uint32_t)__bfloat16_as_ushort(h3) << 16);
            __nv_bfloat16 q0 = __float2bfloat16(l0), q1 = __float2bfloat16(l1);
            __nv_bfloat16 q2 = __float2bfloat16(l2), q3 = __float2bfloat16(l3);
            uint32_t pl0 = (uint32_t)__bfloat16_as_ushort(q0) | ((uint32_t)__bfloat16_as_ushort(q1) << 16);
            uint32_t pl1 = (uint32_t)__bfloat16_as_ushort(q2) | ((uint32_t)__bfloat16_as_ushort(q3) << 16);
            *(uint2*)(sAhi + row * ASTRIDE + c4) = make_uint2(ph0, ph1);
            *(uint2*)(sAlo + row * ASTRIDE + c4) = make_uint2(pl0, pl1);
        }
        // ---- load B tile: Whi/Wlo[128 x 32] bf16 (uint4 = 8 bf16)
        #pragma unroll
        for (int i = 0; i < 2; i++) {
            int idx = i * 256 + tid;
            int row = idx >> 2, c8 = (idx & 3) * 8;
            uint4 vh = *(const uint4*)(g_Whi + (size_t)(bx * 128 + row) * MD + k0 + c8);
            uint4 vl = *(const uint4*)(g_Wlo + (size_t)(bx * 128 + row) * MD + k0 + c8);
            *(uint4*)(sBhi + row * ASTRIDE + c8) = vh;
            *(uint4*)(sBlo + row * ASTRIDE + c8) = vl;
        }
        __syncthreads();

        #pragma unroll
        for (int ks = 0; ks < 2; ks++) {
            uint32_t ahi[2][4], alo[2][4];
            #pragma unroll
            for (int mt = 0; mt < 2; mt++) {
                uint32_t off = (uint32_t)((warpM * 32 + mt * 16 + aRow) * 80) +
                               (uint32_t)(ks * 32) + aByte;
                LDSM4(ahi[mt][0], ahi[mt][1], ahi[mt][2], ahi[mt][3], aHb + off);
                LDSM4(alo[mt][0], alo[mt][1], alo[mt][2], alo[mt][3], aLb + off);
            }
            #pragma unroll
            for (int nf2 = 0; nf2 < 4; nf2++) {
                uint32_t off = (uint32_t)((bRow + nf2 * 16) * 80) +
                               (uint32_t)(ks * 32) + bByte;
                uint32_t bh[4], bl[4];
                LDSM4(bh[0], bh[1], bh[2], bh[3], bHb + off);
                LDSM4(bl[0], bl[1], bl[2], bl[3], bLb + off);
                #pragma unroll
                for (int half = 0; half < 2; half++) {
                    int nf = nf2 * 2 + half;
                    uint32_t bhi2[2] = { bh[half * 2], bh[half * 2 + 1] };
                    uint32_t blo2[2] = { bl[half * 2], bl[half * 2 + 1] };
                    #pragma unroll
                    for (int mt = 0; mt < 2; mt++) {
                        MMA16816(acc[mt][nf], ahi[mt], bhi2);
                        MMA16816(acc[mt][nf], ahi[mt], blo2);
                        MMA16816(acc[mt][nf], alo[mt], bhi2);
                    }
                }
            }
        }
    }

    // ---- epilogue: bias + store to g_h
    const int qr = lane >> 2, qc = (lane & 3) * 2;
    #pragma unroll
    for (int mt = 0; mt < 2; mt++) {
        int r0 = by * 128 + warpM * 32 + mt * 16 + qr;
        #pragma unroll
        for (int nf = 0; nf < 8; nf++) {
            int c = bx * 128 + warpN * 64 + nf * 8 + qc;
            float b0 = __ldg(bias + c), b1 = __ldg(bias + c + 1);
            g_h[(size_t)r0 * PD + c]           = acc[mt][nf][0] + b0;
            g_h[(size_t)r0 * PD + c + 1]       = acc[mt][nf][1] + b1;
            g_h[(size_t)(r0 + 8) * PD + c]     = acc[mt][nf][2] + b0;
            g_h[(size_t)(r0 + 8) * PD + c + 1] = acc[mt][nf][3] + b1;
        }
    }
}

// ---------------- per-token epilogue (warp per token) ----------------
__global__ void __launch_bounds__(256)
epilogue_kernel(const float* __restrict__ mask,
                float* __restrict__ out_logits,
                float* __restrict__ out_topk,
                int write_topk) {
    __shared__ float sT[32 * PD];
    __shared__ float sc[8][NE];

    const int t = threadIdx.x;
    const int warp = t >> 5, lane = t & 31;
    const int token = blockIdx.x * 8 + warp;

    const float* hrow = g_h + (size_t)token * PD + lane * 8;
    float h[8];
    *(float4*)(h)     = *(const float4*)(hrow);
    *(float4*)(h + 4) = *(const float4*)(hrow + 4);

    float ss = 0.f;
    #pragma unroll
    for (int j = 0; j < 8; j++) ss += h[j] * h[j];
    #pragma unroll
    for (int o = 16; o > 0; o >>= 1) ss += __shfl_xor_sync(0xffffffffu, ss, o);
    const float inv = 1.f / fmaxf(sqrtf(ss), 1e-12f);
    const float scale = g_scale;

    float lg[2] = {0.f, 0.f};
    for (int c = 0; c < 2; c++) {
        __syncthreads();
        const float4* src = (const float4*)(g_simnT + c * 32 * PD);
        float4* dst = (float4*)sT;
        #pragma unroll
        for (int i = 0; i < 8; i++) dst[t + i * 256] = src[t + i * 256];
        __syncthreads();

        #pragma unroll
        for (int el = 0; el < 32; el++) {
            const float* sp = sT + el * PD + lane * 8;
            float s0[8];
            *(float4*)(s0)     = *(const float4*)(sp);
            *(float4*)(s0 + 4) = *(const float4*)(sp + 4);
            float d = 0.f;
            #pragma unroll
            for (int j = 0; j < 8; j++) d = fmaf(h[j], s0[j], d);
            #pragma unroll
            for (int o = 16; o > 0; o >>= 1) d += __shfl_xor_sync(0xffffffffu, d, o);
            if (lane == el) lg[c] = d;
        }
    }

    float l0 = lg[0] * inv * scale;
    float l1 = lg[1] * inv * scale;
    if (__ldg(mask + lane) == 0.f)      l0 = -1e9f;
    if (__ldg(mask + lane + 32) == 0.f) l1 = -1e9f;

    out_logits[(size_t)token * NE + lane]      = l0;
    out_logits[(size_t)token * NE + lane + 32] = l1;

    if (!write_topk) return;

    float m = fmaxf(l0, l1);
    #pragma unroll
    for (int o = 16; o > 0; o >>= 1) m = fmaxf(m, __shfl_xor_sync(0xffffffffu, m, o));
    float e0 = expf(l0 - m), e1 = expf(l1 - m);
    float sum = e0 + e1;
    #pragma unroll
    for (int o = 16; o > 0; o >>= 1) sum += __shfl_xor_sync(0xffffffffu, sum, o);
    float invs = 1.f / sum;
    float p0 = e0 * invs + 1e-14f;
    float p1 = e1 * invs + 1e-14f;

    sc[warp][lane]      = p0;
    sc[warp][lane + 32] = p1;
    __syncwarp();

    float a0 = 0.f, a1 = 0.f;
    const int i0 = lane, i1 = lane + 32;
    #pragma unroll 8
    for (int j = 0; j < NE; j++) {
        float v = sc[warp][j];
        if (v > p0 || (v == p0 && j < i0)) a0 += v;
        if (v > p1 || (v == p1 && j < i1)) a1 += v;
    }
    int k = (a0 < 1.f) + (a1 < 1.f);
    #pragma unroll
    for (int o = 16; o > 0; o >>= 1) k += __shfl_xor_sync(0xffffffffu, k, o);

    if (lane == 0)
        out_topk[token] = fminf((float)k, g_active);
}

// ---------------- launch ----------------
extern "C" void kernel_launch(void* const* d_in, const int* in_sizes, int n_in,
                              void* d_out, int out_size) {
    const float* x    = (const float*)d_in[0];
    const float* W    = (const float*)d_in[1];
    const float* b    = (const float*)d_in[2];
    const float* sim  = (const float*)d_in[3];
    const float* temp = (const float*)d_in[4];
    const float* mask = (const float*)d_in[5];
    float* out = (float*)d_out;

    convert_w_kernel<<<256, 256>>>(W);
    prep_kernel<<<1, 256>>>(sim, temp, mask);

    dim3 grid(PD / 128, NTOK / 128);
    mma_gemm1_kernel<<<grid, 256>>>(x, b);

    const int logits_elems = NTOK * NE;
    int write_topk = (out_size >= logits_elems + NTOK) ? 1 : 0;
    epilogue_kernel<<<NTOK / 8, 256>>>(mask, out, out + logits_elems, write_topk);
}

// round 5
// speedup vs baseline: 1.3461x; 1.3461x over previous
#include <cuda_runtime.h>
#include <cuda_bf16.h>
#include <cstdint>

#define NTOK 16384
#define MD   2048
#define PD   256
#define NE   64

// ---------------- device globals ----------------
__device__ __align__(16) __nv_bfloat16 g_hhi[NTOK * PD];
__device__ __align__(16) __nv_bfloat16 g_hlo[NTOK * PD];
__device__ __align__(16) __nv_bfloat16 g_Whi[PD * MD];
__device__ __align__(16) __nv_bfloat16 g_Wlo[PD * MD];
__device__ __align__(16) __nv_bfloat16 g_simHi[NE * PD];
__device__ __align__(16) __nv_bfloat16 g_simLo[NE * PD];
__device__ float g_scale;
__device__ float g_active;

// ---------------- helpers ----------------
__device__ __forceinline__ uint32_t smem_u32(const void* p) {
    uint32_t a;
    asm("{ .reg .u64 t; cvta.to.shared.u64 t, %1; cvt.u32.u64 %0, t; }" : "=r"(a) : "l"(p));
    return a;
}
#define LDSM4(r0, r1, r2, r3, a)                                                  \
    asm volatile("ldmatrix.sync.aligned.m8n8.x4.shared.b16 {%0,%1,%2,%3}, [%4];" \
                 : "=r"(r0), "=r"(r1), "=r"(r2), "=r"(r3) : "r"(a))
#define MMA16816(c, a, b)                                                         \
    asm volatile("mma.sync.aligned.m16n8k16.row.col.f32.bf16.bf16.f32 "           \
                 "{%0,%1,%2,%3}, {%4,%5,%6,%7}, {%8,%9}, {%0,%1,%2,%3};"          \
                 : "+f"((c)[0]), "+f"((c)[1]), "+f"((c)[2]), "+f"((c)[3])         \
                 : "r"((a)[0]), "r"((a)[1]), "r"((a)[2]), "r"((a)[3]),            \
                   "r"((b)[0]), "r"((b)[1]))
#define CP16(dst, src) asm volatile("cp.async.cg.shared.global [%0], [%1], 16;" :: "r"(dst), "l"(src))
#define CP_COMMIT()    asm volatile("cp.async.commit_group;" ::: "memory")
#define CP_WAIT0()     asm volatile("cp.async.wait_group 0;" ::: "memory")

__device__ __forceinline__ uint32_t pack_hi(float v0, float v1, float& l0, float& l1) {
    __nv_bfloat16 h0 = __float2bfloat16(v0), h1 = __float2bfloat16(v1);
    l0 = v0 - __bfloat162float(h0);
    l1 = v1 - __bfloat162float(h1);
    return (uint32_t)__bfloat16_as_ushort(h0) | ((uint32_t)__bfloat16_as_ushort(h1) << 16);
}
__device__ __forceinline__ uint32_t pack_bf2(float v0, float v1) {
    return (uint32_t)__bfloat16_as_ushort(__float2bfloat16(v0)) |
           ((uint32_t)__bfloat16_as_ushort(__float2bfloat16(v1)) << 16);
}

// ---------------- prep kernels ----------------
__global__ void convert_w_kernel(const float* __restrict__ W) {
    int base = blockIdx.x * 2048 + threadIdx.x;
    #pragma unroll
    for (int i = 0; i < 8; i++) {
        int e = base + i * 256;
        float v = W[e];
        __nv_bfloat16 h = __float2bfloat16(v);
        g_Whi[e] = h;
        g_Wlo[e] = __float2bfloat16(v - __bfloat162float(h));
    }
}
__global__ void prep_kernel(const float* __restrict__ sim,
                            const float* __restrict__ temperature,
                            const float* __restrict__ mask) {
    int e = threadIdx.x;  // 0..63
    float ss = 0.f;
    #pragma unroll 8
    for (int p = 0; p < PD; p++) {
        float v = sim[p * NE + e];
        ss += v * v;
    }
    float inv = 1.f / fmaxf(sqrtf(ss), 1e-12f);
    #pragma unroll 4
    for (int p = 0; p < PD; p++) {
        float v = sim[p * NE + e] * inv;
        __nv_bfloat16 h = __float2bfloat16(v);
        g_simHi[e * PD + p] = h;
        g_simLo[e * PD + p] = __float2bfloat16(v - __bfloat162float(h));
    }
    if (e == 0) {
        float a = 0.f;
        for (int i = 0; i < NE; i++) a += mask[i];
        g_active = a;
        g_scale = expf(fminf(temperature[0], 4.6051701859880913680f));
    }
}

// ---------------- GEMM1: h = x @ W^T + b, BM=128 BN=256 BK=32, pipelined ----------------
#define BK 32
#define G1_AHI 0
#define G1_ALO 10240
#define G1_BHI 20480
#define G1_BLO 40960
#define G1_STAGE 61440
#define G1_SMEM (2 * G1_STAGE)

__global__ void __launch_bounds__(256, 1)
mma_gemm1_kernel(const float* __restrict__ X, const float* __restrict__ bias) {
    extern __shared__ __align__(16) char dsm[];
    const uint32_t sb = smem_u32(dsm);

    const int tid = threadIdx.x;
    const int wid = tid >> 5, lane = tid & 31;
    const int warpM = wid & 3;        // 4 x 32 rows
    const int warpN = wid >> 2;       // 2 x 128 cols
    const int by = blockIdx.x;        // 0..127

    const uint32_t aRow  = (uint32_t)(lane & 15);
    const uint32_t aByte = (uint32_t)((lane >> 4) * 16);
    const int g = lane >> 3;
    const uint32_t bRowBase = (uint32_t)(((g >> 1) << 3) + (lane & 7));
    const uint32_t bByte = (uint32_t)((g & 1) * 16);

    // load-index precompute
    const int aRowL = tid >> 3, aC4 = (tid & 7) * 4;        // + i*32 rows
    const int bRowL = tid >> 2, bC8 = (tid & 3) * 8;        // + i*64 rows

    float acc[2][16][4];
    #pragma unroll
    for (int i = 0; i < 2; i++)
        #pragma unroll
        for (int j = 0; j < 16; j++)
            #pragma unroll
            for (int q = 0; q < 4; q++) acc[i][j][q] = 0.f;

    const float* Xb = X + (size_t)by * 128 * MD;

    float4 aReg[4];
    // prologue: A(0) into regs, cp.async B(0) into stage 0
    #pragma unroll
    for (int i = 0; i < 4; i++)
        aReg[i] = *(const float4*)(Xb + (size_t)(aRowL + i * 32) * MD + aC4);
    #pragma unroll
    for (int i = 0; i < 4; i++) {
        int row = bRowL + i * 64;
        uint32_t dH = sb + G1_BHI + (uint32_t)(row * 80 + bC8 * 2);
        uint32_t dL = sb + G1_BLO + (uint32_t)(row * 80 + bC8 * 2);
        CP16(dH, g_Whi + (size_t)row * MD + bC8);
        CP16(dL, g_Wlo + (size_t)row * MD + bC8);
    }
    CP_COMMIT();

    for (int kc = 0; kc < MD / BK; kc++) {
        const int s = kc & 1;
        char* st = dsm + s * G1_STAGE;
        const uint32_t stu = sb + s * G1_STAGE;

        // convert + STS A from regs
        #pragma unroll
        for (int i = 0; i < 4; i++) {
            float4 v = aReg[i];
            float l0, l1, l2, l3;
            uint32_t ph0 = pack_hi(v.x, v.y, l0, l1);
            uint32_t ph1 = pack_hi(v.z, v.w, l2, l3);
            uint32_t pl0 = pack_bf2(l0, l1);
            uint32_t pl1 = pack_bf2(l2, l3);
            int row = aRowL + i * 32;
            *(uint2*)(st + G1_AHI + row * 80 + aC4 * 2) = make_uint2(ph0, ph1);
            *(uint2*)(st + G1_ALO + row * 80 + aC4 * 2) = make_uint2(pl0, pl1);
        }
        CP_WAIT0();
        __syncthreads();

        if (kc + 1 < MD / BK) {
            const int k0n = (kc + 1) * BK;
            #pragma unroll
            for (int i = 0; i < 4; i++)
                aReg[i] = *(const float4*)(Xb + (size_t)(aRowL + i * 32) * MD + k0n + aC4);
            const uint32_t stn = sb + (s ^ 1) * G1_STAGE;
            #pragma unroll
            for (int i = 0; i < 4; i++) {
                int row = bRowL + i * 64;
                uint32_t dH = stn + G1_BHI + (uint32_t)(row * 80 + bC8 * 2);
                uint32_t dL = stn + G1_BLO + (uint32_t)(row * 80 + bC8 * 2);
                CP16(dH, g_Whi + (size_t)row * MD + k0n + bC8);
                CP16(dL, g_Wlo + (size_t)row * MD + k0n + bC8);
            }
            CP_COMMIT();
        }

        // MMA phase
        #pragma unroll
        for (int ks = 0; ks < 2; ks++) {
            uint32_t ahi[2][4], alo[2][4];
            #pragma unroll
            for (int mt = 0; mt < 2; mt++) {
                uint32_t off = (uint32_t)((warpM * 32 + mt * 16 + aRow) * 80) +
                               (uint32_t)(ks * 32) + aByte;
                LDSM4(ahi[mt][0], ahi[mt][1], ahi[mt][2], ahi[mt][3], stu + G1_AHI + off);
                LDSM4(alo[mt][0], alo[mt][1], alo[mt][2], alo[mt][3], stu + G1_ALO + off);
            }
            #pragma unroll
            for (int nf2 = 0; nf2 < 8; nf2++) {
                uint32_t off = (uint32_t)((warpN * 128 + nf2 * 16 + bRowBase) * 80) +
                               (uint32_t)(ks * 32) + bByte;
                uint32_t bh[4], bl[4];
                LDSM4(bh[0], bh[1], bh[2], bh[3], stu + G1_BHI + off);
                LDSM4(bl[0], bl[1], bl[2], bl[3], stu + G1_BLO + off);
                #pragma unroll
                for (int half = 0; half < 2; half++) {
                    int nf = nf2 * 2 + half;
                    uint32_t b2h[2] = { bh[half * 2], bh[half * 2 + 1] };
                    uint32_t b2l[2] = { bl[half * 2], bl[half * 2 + 1] };
                    #pragma unroll
                    for (int mt = 0; mt < 2; mt++) {
                        MMA16816(acc[mt][nf], ahi[mt], b2h);
                        MMA16816(acc[mt][nf], ahi[mt], b2l);
                        MMA16816(acc[mt][nf], alo[mt], b2h);
                    }
                }
            }
        }
    }

    // epilogue: bias, split to bf16 hi/lo, store
    const int qr = lane >> 2, qc = (lane & 3) * 2;
    #pragma unroll
    for (int mt = 0; mt < 2; mt++) {
        int r0 = by * 128 + warpM * 32 + mt * 16 + qr;
        #pragma unroll
        for (int nf = 0; nf < 16; nf++) {
            int c = warpN * 128 + nf * 8 + qc;
            float b0 = __ldg(bias + c), b1 = __ldg(bias + c + 1);
            float v00 = acc[mt][nf][0] + b0, v01 = acc[mt][nf][1] + b1;
            float v10 = acc[mt][nf][2] + b0, v11 = acc[mt][nf][3] + b1;
            float l0, l1;
            uint32_t h0 = pack_hi(v00, v01, l0, l1);
            *(uint32_t*)(g_hhi + (size_t)r0 * PD + c) = h0;
            *(uint32_t*)(g_hlo + (size_t)r0 * PD + c) = pack_bf2(l0, l1);
            uint32_t h1 = pack_hi(v10, v11, l0, l1);
            *(uint32_t*)(g_hhi + (size_t)(r0 + 8) * PD + c) = h1;
            *(uint32_t*)(g_hlo + (size_t)(r0 + 8) * PD + c) = pack_bf2(l0, l1);
        }
    }
}

// ---------------- epilogue: logits MMA + softmax + topk, 128 tokens/block ----------------
#define HS 264                      // smem stride (elems) for 256-col tiles
#define E_HHI 0
#define E_HLO 67584
#define E_SHI 135168
#define E_SLO 168960
#define E_SINV 202752               // 128 f32
#define E_MASK 203264               // 64 f32
#define E_SC   0                    // overlay over hHi after MMA
#define E_SMEM 203520

__global__ void __launch_bounds__(256, 1)
epilogue_kernel(const float* __restrict__ mask,
                float* __restrict__ out_logits,
                float* __restrict__ out_topk,
                int write_topk) {
    extern __shared__ __align__(16) char dsm[];
    const uint32_t sb = smem_u32(dsm);
    const int tid = threadIdx.x;
    const int wid = tid >> 5, lane = tid & 31;
    const int blk = blockIdx.x;
    const int tokBase = blk * 128;

    // ---- stage h tile (hi/lo) and sim (hi/lo)
    #pragma unroll
    for (int i = 0; i < 16; i++) {
        int idx = i * 256 + tid;                 // 4096 chunks of 8 bf16
        int row = idx >> 5, c8 = (idx & 31) * 8;
        uint4 vh = *(const uint4*)(g_hhi + (size_t)(tokBase + row) * PD + c8);
        uint4 vl = *(const uint4*)(g_hlo + (size_t)(tokBase + row) * PD + c8);
        *(uint4*)(dsm + E_HHI + (row * HS + c8) * 2) = vh;
        *(uint4*)(dsm + E_HLO + (row * HS + c8) * 2) = vl;
    }
    #pragma unroll
    for (int i = 0; i < 8; i++) {
        int idx = i * 256 + tid;                 // 2048 chunks
        int row = idx >> 5, c8 = (idx & 31) * 8;
        uint4 vh = *(const uint4*)(g_simHi + (size_t)row * PD + c8);
        uint4 vl = *(const uint4*)(g_simLo + (size_t)row * PD + c8);
        *(uint4*)(dsm + E_SHI + (row * HS + c8) * 2) = vh;
        *(uint4*)(dsm + E_SLO + (row * HS + c8) * 2) = vl;
    }
    if (tid < NE) ((float*)(dsm + E_MASK))[tid] = mask[tid];
    __syncthreads();

    // ---- per-row inv-norm * scale
    const float scale = g_scale;
    #pragma unroll
    for (int i = 0; i < 16; i++) {
        int row = wid * 16 + i;
        const __nv_bfloat16* ph = (const __nv_bfloat16*)(dsm + E_HHI) + row * HS + lane * 8;
        const __nv_bfloat16* pl = (const __nv_bfloat16*)(dsm + E_HLO) + row * HS + lane * 8;
        uint4 vh = *(const uint4*)ph;
        uint4 vl = *(const uint4*)pl;
        const __nv_bfloat16* hh = (const __nv_bfloat16*)&vh;
        const __nv_bfloat16* ll = (const __nv_bfloat16*)&vl;
        float ss = 0.f;
        #pragma unroll
        for (int j = 0; j < 8; j++) {
            float v = __bfloat162float(hh[j]) + __bfloat162float(ll[j]);
            ss += v * v;
        }
        #pragma unroll
        for (int o = 16; o > 0; o >>= 1) ss += __shfl_xor_sync(0xffffffffu, ss, o);
        if (lane == 0)
            ((float*)(dsm + E_SINV))[row] = scale / fmaxf(sqrtf(ss), 1e-12f);
    }
    __syncthreads();

    // ---- MMA: [16 rows/warp] x [64 experts] x K=256, 3-term split
    const uint32_t aRow  = (uint32_t)(lane & 15);
    const uint32_t aByte = (uint32_t)((lane >> 4) * 16);
    const int g = lane >> 3;
    const uint32_t bRowBase = (uint32_t)(((g >> 1) << 3) + (lane & 7));
    const uint32_t bByte = (uint32_t)((g & 1) * 16);
    const int warpRow = wid * 16;

    float acc[8][4];
    #pragma unroll
    for (int j = 0; j < 8; j++)
        #pragma unroll
        for (int q = 0; q < 4; q++) acc[j][q] = 0.f;

    #pragma unroll
    for (int ks = 0; ks < 16; ks++) {
        uint32_t ahi[4], alo[4];
        uint32_t aoff = (uint32_t)((warpRow + aRow) * HS * 2) + (uint32_t)(ks * 32) + aByte;
        LDSM4(ahi[0], ahi[1], ahi[2], ahi[3], sb + E_HHI + aoff);
        LDSM4(alo[0], alo[1], alo[2], alo[3], sb + E_HLO + aoff);
        #pragma unroll
        for (int nf2 = 0; nf2 < 4; nf2++) {
            uint32_t boff = (uint32_t)((nf2 * 16 + bRowBase) * HS * 2) +
                            (uint32_t)(ks * 32) + bByte;
            uint32_t bh[4], bl[4];
            LDSM4(bh[0], bh[1], bh[2], bh[3], sb + E_SHI + boff);
            LDSM4(bl[0], bl[1], bl[2], bl[3], sb + E_SLO + boff);
            #pragma unroll
            for (int half = 0; half < 2; half++) {
                int nf = nf2 * 2 + half;
                uint32_t b2h[2] = { bh[half * 2], bh[half * 2 + 1] };
                uint32_t b2l[2] = { bl[half * 2], bl[half * 2 + 1] };
                MMA16816(acc[nf], ahi, b2h);
                MMA16816(acc[nf], ahi, b2l);
                MMA16816(acc[nf], alo, b2h);
            }
        }
    }
    __syncthreads();   // all MMAs done before sc overlays hHi

    // ---- scale, mask, logits out, softmax, stage probs
    const int qr = lane >> 2, qc = (lane & 3) * 2;
    const int r0 = warpRow + qr, r1 = r0 + 8;
    const float inv0 = ((float*)(dsm + E_SINV))[r0];
    const float inv1 = ((float*)(dsm + E_SINV))[r1];
    const float* maskS = (const float*)(dsm + E_MASK);

    float p0[16], p1[16];
    #pragma unroll
    for (int nf = 0; nf < 8; nf++) {
        int c = nf * 8 + qc;
        bool m0 = maskS[c] == 0.f, m1 = maskS[c + 1] == 0.f;
        float a = m0 ? -1e9f : acc[nf][0] * inv0;
        float b = m1 ? -1e9f : acc[nf][1] * inv0;
        float cc = m0 ? -1e9f : acc[nf][2] * inv1;
        float dd = m1 ? -1e9f : acc[nf][3] * inv1;
        p0[nf * 2] = a; p0[nf * 2 + 1] = b;
        p1[nf * 2] = cc; p1[nf * 2 + 1] = dd;
        *(float2*)(out_logits + (size_t)(tokBase + r0) * NE + c) = make_float2(a, b);
        *(float2*)(out_logits + (size_t)(tokBase + r1) * NE + c) = make_float2(cc, dd);
    }

    if (write_topk) {
        // softmax per row across quad (lanes qr*4..qr*4+3)
        float m0 = -1e30f, m1 = -1e30f;
        #pragma unroll
        for (int j = 0; j < 16; j++) { m0 = fmaxf(m0, p0[j]); m1 = fmaxf(m1, p1[j]); }
        #pragma unroll
        for (int o = 1; o < 4; o <<= 1) {
            m0 = fmaxf(m0, __shfl_xor_sync(0xffffffffu, m0, o));
            m1 = fmaxf(m1, __shfl_xor_sync(0xffffffffu, m1, o));
        }
        float s0 = 0.f, s1 = 0.f;
        #pragma unroll
        for (int j = 0; j < 16; j++) {
            p0[j] = __expf(p0[j] - m0); s0 += p0[j];
            p1[j] = __expf(p1[j] - m1); s1 += p1[j];
        }
        #pragma unroll
        for (int o = 1; o < 4; o <<= 1) {
            s0 += __shfl_xor_sync(0xffffffffu, s0, o);
            s1 += __shfl_xor_sync(0xffffffffu, s1, o);
        }
        float is0 = 1.f / s0, is1 = 1.f / s1;
        float* sc = (float*)(dsm + E_SC);
        #pragma unroll
        for (int nf = 0; nf < 8; nf++) {
            int c = nf * 8 + qc;
            *(float2*)(sc + r0 * 68 + c) =
                make_float2(p0[nf * 2] * is0 + 1e-14f, p0[nf * 2 + 1] * is0 + 1e-14f);
            *(float2*)(sc + r1 * 68 + c) =
                make_float2(p1[nf * 2] * is1 + 1e-14f, p1[nf * 2 + 1] * is1 + 1e-14f);
        }
        __syncthreads();

        if (tid < 128) {
            const float* row = sc + tid * 68;
            float v[64];
            #pragma unroll
            for (int i = 0; i < 16; i++)
                *(float4*)(v + i * 4) = *(const float4*)(row + i * 4);
            // bitonic ascending
            #pragma unroll
            for (int k = 2; k <= 64; k <<= 1)
                #pragma unroll
                for (int j = k >> 1; j > 0; j >>= 1)
                    #pragma unroll
                    for (int i = 0; i < 64; i++) {
                        int p = i ^ j;
                        if (p > i) {
                            bool up = ((i & k) == 0);
                            float a = v[i], b = v[p];
                            bool sw = up ? (a > b) : (a < b);
                            float lo = sw ? b : a, hi = sw ? a : b;
                            v[i] = lo; v[p] = hi;
                        }
                    }
            float cum = 0.f; int k = 0;
            #pragma unroll
            for (int r = 63; r >= 0; r--) { if (cum < 1.f) k++; cum += v[r]; }
            out_topk[tokBase + tid] = fminf((float)k, g_active);
        }
    }
}

// ---------------- launch ----------------
extern "C" void kernel_launch(void* const* d_in, const int* in_sizes, int n_in,
                              void* d_out, int out_size) {
    const float* x    = (const float*)d_in[0];
    const float* W    = (const float*)d_in[1];
    const float* b    = (const float*)d_in[2];
    const float* sim  = (const float*)d_in[3];
    const float* temp = (const float*)d_in[4];
    const float* mask = (const float*)d_in[5];
    float* out = (float*)d_out;

    cudaFuncSetAttribute(mma_gemm1_kernel, cudaFuncAttributeMaxDynamicSharedMemorySize, G1_SMEM);
    cudaFuncSetAttribute(epilogue_kernel, cudaFuncAttributeMaxDynamicSharedMemorySize, E_SMEM);

    convert_w_kernel<<<256, 256>>>(W);
    prep_kernel<<<1, 64>>>(sim, temp, mask);

    mma_gemm1_kernel<<<NTOK / 128, 256, G1_SMEM>>>(x, b);

    const int logits_elems = NTOK * NE;
    int write_topk = (out_size >= logits_elems + NTOK) ? 1 : 0;
    epilogue_kernel<<<NTOK / 128, 256, E_SMEM>>>(mask, out, out + logits_elems, write_topk);
}

// round 7
// speedup vs baseline: 1.4059x; 1.0444x over previous
#include <cuda_runtime.h>
#include <cuda_bf16.h>
#include <cstdint>

#define NTOK 16384
#define MD   2048
#define PD   256
#define NE   64
#define BK   32

// ---------------- device globals ----------------
__device__ __align__(16) __nv_bfloat16 g_Whi[PD * MD];
__device__ __align__(16) __nv_bfloat16 g_Wlo[PD * MD];
__device__ __align__(16) __nv_bfloat16 g_simHi[NE * PD];
__device__ __align__(16) __nv_bfloat16 g_simLo[NE * PD];
__device__ float g_scale;
__device__ float g_active;

// ---------------- helpers ----------------
__device__ __forceinline__ uint32_t smem_u32(const void* p) {
    uint32_t a;
    asm("{ .reg .u64 t; cvta.to.shared.u64 t, %1; cvt.u32.u64 %0, t; }" : "=r"(a) : "l"(p));
    return a;
}
#define LDSM4(r0, r1, r2, r3, a)                                                  \
    asm volatile("ldmatrix.sync.aligned.m8n8.x4.shared.b16 {%0,%1,%2,%3}, [%4];" \
                 : "=r"(r0), "=r"(r1), "=r"(r2), "=r"(r3) : "r"(a))
#define MMA16816(c, a, b)                                                         \
    asm volatile("mma.sync.aligned.m16n8k16.row.col.f32.bf16.bf16.f32 "           \
                 "{%0,%1,%2,%3}, {%4,%5,%6,%7}, {%8,%9}, {%0,%1,%2,%3};"          \
                 : "+f"((c)[0]), "+f"((c)[1]), "+f"((c)[2]), "+f"((c)[3])         \
                 : "r"((a)[0]), "r"((a)[1]), "r"((a)[2]), "r"((a)[3]),            \
                   "r"((b)[0]), "r"((b)[1]))
#define CP16(dst, src) asm volatile("cp.async.cg.shared.global [%0], [%1], 16;" :: "r"(dst), "l"(src))
#define CP_COMMIT()    asm volatile("cp.async.commit_group;" ::: "memory")
#define CP_WAIT0()     asm volatile("cp.async.wait_group 0;" ::: "memory")

__device__ __forceinline__ uint32_t pack_hi(float v0, float v1, float& l0, float& l1) {
    __nv_bfloat16 h0 = __float2bfloat16(v0), h1 = __float2bfloat16(v1);
    l0 = v0 - __bfloat162float(h0);
    l1 = v1 - __bfloat162float(h1);
    return (uint32_t)__bfloat16_as_ushort(h0) | ((uint32_t)__bfloat16_as_ushort(h1) << 16);
}
__device__ __forceinline__ uint32_t pack_bf2(float v0, float v1) {
    return (uint32_t)__bfloat16_as_ushort(__float2bfloat16(v0)) |
           ((uint32_t)__bfloat16_as_ushort(__float2bfloat16(v1)) << 16);
}

// ---------------- prep kernels ----------------
__global__ void convert_w_kernel(const float* __restrict__ W) {
    int base = blockIdx.x * 2048 + threadIdx.x;
    #pragma unroll
    for (int i = 0; i < 8; i++) {
        int e = base + i * 256;
        float v = W[e];
        __nv_bfloat16 h = __float2bfloat16(v);
        g_Whi[e] = h;
        g_Wlo[e] = __float2bfloat16(v - __bfloat162float(h));
    }
}
__global__ void prep_kernel(const float* __restrict__ sim,
                            const float* __restrict__ temperature,
                            const float* __restrict__ mask) {
    int e = threadIdx.x;  // 0..63
    float ss = 0.f;
    #pragma unroll 8
    for (int p = 0; p < PD; p++) {
        float v = sim[p * NE + e];
        ss += v * v;
    }
    float inv = 1.f / fmaxf(sqrtf(ss), 1e-12f);
    #pragma unroll 4
    for (int p = 0; p < PD; p++) {
        float v = sim[p * NE + e] * inv;
        __nv_bfloat16 h = __float2bfloat16(v);
        g_simHi[e * PD + p] = h;
        g_simLo[e * PD + p] = __float2bfloat16(v - __bfloat162float(h));
    }
    if (e == 0) {
        float a = 0.f;
        for (int i = 0; i < NE; i++) a += mask[i];
        g_active = a;
        g_scale = expf(fminf(temperature[0], 4.6051701859880913680f));
    }
}

// ---------------- smem layout (bytes) ----------------
// mainloop: 2 stages of (Ahi 10240 | Alo 10240 | Bhi 20480 | Blo 20480)
#define G1_AHI 0
#define G1_ALO 10240
#define G1_BHI 20480
#define G1_BLO 40960
#define G1_STAGE 61440
// tail overlay over the stage region:
#define SHI_B   0          // sim hi: 64 rows x 264 elems x 2B = 33792
#define SLO_B   33792
#define CBUF_B  67584      // 128 x 68 f32 = 34816
#define SCBUF_B 102400     // 128 x 68 f32 = 34816 (end 137216)
// extras beyond stage region:
#define BIAS_B  137216     // 256 f32
#define MASK_B  138240     // 64 f32
#define NORM_B  138496     // 128 x 2 f32
#define SINV_B  139520     // 128 f32
#define SMEM_TOTAL 140032

// ---------------- fused kernel ----------------
__global__ void __launch_bounds__(256, 1)
fused_kernel(const float* __restrict__ X, const float* __restrict__ bias,
             const float* __restrict__ mask,
             float* __restrict__ out_logits, float* __restrict__ out_topk,
             int write_topk) {
    extern __shared__ __align__(16) char dsm[];
    const uint32_t sb = smem_u32(dsm);

    const int tid = threadIdx.x;
    const int wid = tid >> 5, lane = tid & 31;
    const int warpM = wid & 3;    // 4 x 32 rows
    const int warpN = wid >> 2;   // 2 x 128 cols
    const int by = blockIdx.x;
    const int tokBase = by * 128;

    const uint32_t aRow  = (uint32_t)(lane & 15);
    const uint32_t aByte = (uint32_t)((lane >> 4) * 16);
    const int gq = lane >> 3;
    const uint32_t bRowBase = (uint32_t)(((gq >> 1) << 3) + (lane & 7));
    const uint32_t bByte = (uint32_t)((gq & 1) * 16);

    const int aRowL = tid >> 3, aC4 = (tid & 7) * 4;
    const int bRowL = tid >> 2, bC8 = (tid & 3) * 8;

    float acc[2][16][4];
    #pragma unroll
    for (int i = 0; i < 2; i++)
        #pragma unroll
        for (int j = 0; j < 16; j++)
            #pragma unroll
            for (int q = 0; q < 4; q++) acc[i][j][q] = 0.f;

    const float* Xb = X + (size_t)by * 128 * MD;

    float4 aReg[4];
    #pragma unroll
    for (int i = 0; i < 4; i++)
        aReg[i] = *(const float4*)(Xb + (size_t)(aRowL + i * 32) * MD + aC4);
    #pragma unroll
    for (int i = 0; i < 4; i++) {
        int row = bRowL + i * 64;
        CP16(sb + G1_BHI + (uint32_t)(row * 80 + bC8 * 2), g_Whi + (size_t)row * MD + bC8);
        CP16(sb + G1_BLO + (uint32_t)(row * 80 + bC8 * 2), g_Wlo + (size_t)row * MD + bC8);
    }
    CP_COMMIT();

    // ================= mainloop =================
    for (int kc = 0; kc < MD / BK; kc++) {
        const int s = kc & 1;
        char* st = dsm + s * G1_STAGE;
        const uint32_t stu = sb + s * G1_STAGE;

        #pragma unroll
        for (int i = 0; i < 4; i++) {
            float4 v = aReg[i];
            float l0, l1, l2, l3;
            uint32_t ph0 = pack_hi(v.x, v.y, l0, l1);
            uint32_t ph1 = pack_hi(v.z, v.w, l2, l3);
            uint32_t pl0 = pack_bf2(l0, l1);
            uint32_t pl1 = pack_bf2(l2, l3);
            int row = aRowL + i * 32;
            *(uint2*)(st + G1_AHI + row * 80 + aC4 * 2) = make_uint2(ph0, ph1);
            *(uint2*)(st + G1_ALO + row * 80 + aC4 * 2) = make_uint2(pl0, pl1);
        }
        CP_WAIT0();
        __syncthreads();

        if (kc + 1 < MD / BK) {
            const int k0n = (kc + 1) * BK;
            #pragma unroll
            for (int i = 0; i < 4; i++)
                aReg[i] = *(const float4*)(Xb + (size_t)(aRowL + i * 32) * MD + k0n + aC4);
            const uint32_t stn = sb + (s ^ 1) * G1_STAGE;
            #pragma unroll
            for (int i = 0; i < 4; i++) {
                int row = bRowL + i * 64;
                CP16(stn + G1_BHI + (uint32_t)(row * 80 + bC8 * 2),
                     g_Whi + (size_t)row * MD + k0n + bC8);
                CP16(stn + G1_BLO + (uint32_t)(row * 80 + bC8 * 2),
                     g_Wlo + (size_t)row * MD + k0n + bC8);
            }
            CP_COMMIT();
        }

        // MMA phase: term-major over nf2 pairs, 8-acc rotation
        #pragma unroll
        for (int ks = 0; ks < 2; ks++) {
            uint32_t ahi[2][4], alo[2][4];
            #pragma unroll
            for (int mt = 0; mt < 2; mt++) {
                uint32_t off = (uint32_t)((warpM * 32 + mt * 16 + aRow) * 80) +
                               (uint32_t)(ks * 32) + aByte;
                LDSM4(ahi[mt][0], ahi[mt][1], ahi[mt][2], ahi[mt][3], stu + G1_AHI + off);
                LDSM4(alo[mt][0], alo[mt][1], alo[mt][2], alo[mt][3], stu + G1_ALO + off);
            }
            #pragma unroll
            for (int p = 0; p < 4; p++) {
                uint32_t bh[2][4], bl[2][4];
                #pragma unroll
                for (int j = 0; j < 2; j++) {
                    int nf2 = p * 2 + j;
                    uint32_t off = (uint32_t)((warpN * 128 + nf2 * 16 + bRowBase) * 80) +
                                   (uint32_t)(ks * 32) + bByte;
                    LDSM4(bh[j][0], bh[j][1], bh[j][2], bh[j][3], stu + G1_BHI + off);
                    LDSM4(bl[j][0], bl[j][1], bl[j][2], bl[j][3], stu + G1_BLO + off);
                }
                // term 1: hi*hi over 8 independent accs
                #pragma unroll
                for (int j = 0; j < 2; j++)
                    #pragma unroll
                    for (int half = 0; half < 2; half++)
                        #pragma unroll
                        for (int mt = 0; mt < 2; mt++) {
                            int nf = (p * 2 + j) * 2 + half;
                            uint32_t b2[2] = { bh[j][half * 2], bh[j][half * 2 + 1] };
                            MMA16816(acc[mt][nf], ahi[mt], b2);
                        }
                // term 2: hi*lo
                #pragma unroll
                for (int j = 0; j < 2; j++)
                    #pragma unroll
                    for (int half = 0; half < 2; half++)
                        #pragma unroll
                        for (int mt = 0; mt < 2; mt++) {
                            int nf = (p * 2 + j) * 2 + half;
                            uint32_t b2[2] = { bl[j][half * 2], bl[j][half * 2 + 1] };
                            MMA16816(acc[mt][nf], ahi[mt], b2);
                        }
                // term 3: lo*hi
                #pragma unroll
                for (int j = 0; j < 2; j++)
                    #pragma unroll
                    for (int half = 0; half < 2; half++)
                        #pragma unroll
                        for (int mt = 0; mt < 2; mt++) {
                            int nf = (p * 2 + j) * 2 + half;
                            uint32_t b2[2] = { bh[j][half * 2], bh[j][half * 2 + 1] };
                            MMA16816(acc[mt][nf], alo[mt], b2);
                        }
            }
        }
    }

    // ================= fused tail =================
    __syncthreads();  // done with stage smem

    // stage sim hi/lo (64 x 256, stride 264 elems) + bias + mask
    #pragma unroll
    for (int i = 0; i < 8; i++) {
        int idx = i * 256 + tid;
        int row = idx >> 5, c8 = (idx & 31) * 8;
        *(uint4*)(dsm + SHI_B + row * 528 + c8 * 2) = *(const uint4*)(g_simHi + row * PD + c8);
        *(uint4*)(dsm + SLO_B + row * 528 + c8 * 2) = *(const uint4*)(g_simLo + row * PD + c8);
    }
    ((float*)(dsm + BIAS_B))[tid] = bias[tid];
    if (tid < NE) ((float*)(dsm + MASK_B))[tid] = mask[tid];
    __syncthreads();

    // bias add + row-norm partials
    const float* sBias = (const float*)(dsm + BIAS_B);
    const int qr = lane >> 2, qc = (lane & 3) * 2;
    float ss[4] = {0.f, 0.f, 0.f, 0.f};
    #pragma unroll
    for (int mt = 0; mt < 2; mt++)
        #pragma unroll
        for (int nf = 0; nf < 16; nf++) {
            int c = warpN * 128 + nf * 8 + qc;
            float b0 = sBias[c], b1 = sBias[c + 1];
            acc[mt][nf][0] += b0; acc[mt][nf][1] += b1;
            acc[mt][nf][2] += b0; acc[mt][nf][3] += b1;
            ss[mt * 2]     += acc[mt][nf][0] * acc[mt][nf][0] + acc[mt][nf][1] * acc[mt][nf][1];
            ss[mt * 2 + 1] += acc[mt][nf][2] * acc[mt][nf][2] + acc[mt][nf][3] * acc[mt][nf][3];
        }
    #pragma unroll
    for (int sl = 0; sl < 4; sl++) {
        ss[sl] += __shfl_xor_sync(0xffffffffu, ss[sl], 1);
        ss[sl] += __shfl_xor_sync(0xffffffffu, ss[sl], 2);
    }
    if ((lane & 3) == 0) {
        #pragma unroll
        for (int sl = 0; sl < 4; sl++) {
            int row = warpM * 32 + (sl >> 1) * 16 + qr + (sl & 1) * 8;
            ((float*)(dsm + NORM_B))[row * 2 + warpN] = ss[sl];
        }
    }
    __syncthreads();
    if (tid < 128) {
        const float* nb = (const float*)(dsm + NORM_B);
        float tot = nb[tid * 2] + nb[tid * 2 + 1];
        ((float*)(dsm + SINV_B))[tid] = g_scale / fmaxf(sqrtf(tot), 1e-12f);
    }
    __syncthreads();

    // GEMM2: logits partial [32 rows x 64 experts] over this warp's K half
    float acc2[2][8][4];
    #pragma unroll
    for (int i = 0; i < 2; i++)
        #pragma unroll
        for (int j = 0; j < 8; j++)
            #pragma unroll
            for (int q = 0; q < 4; q++) acc2[i][j][q] = 0.f;

    #pragma unroll
    for (int ks = 0; ks < 8; ks++) {
        uint32_t ahi[2][4], alo[2][4];
        #pragma unroll
        for (int mt = 0; mt < 2; mt++) {
            float l0, l1;
            ahi[mt][0] = pack_hi(acc[mt][2 * ks][0], acc[mt][2 * ks][1], l0, l1);
            alo[mt][0] = pack_bf2(l0, l1);
            ahi[mt][1] = pack_hi(acc[mt][2 * ks][2], acc[mt][2 * ks][3], l0, l1);
            alo[mt][1] = pack_bf2(l0, l1);
            ahi[mt][2] = pack_hi(acc[mt][2 * ks + 1][0], acc[mt][2 * ks + 1][1], l0, l1);
            alo[mt][2] = pack_bf2(l0, l1);
            ahi[mt][3] = pack_hi(acc[mt][2 * ks + 1][2], acc[mt][2 * ks + 1][3], l0, l1);
            alo[mt][3] = pack_bf2(l0, l1);
        }
        #pragma unroll
        for (int ne2 = 0; ne2 < 4; ne2++) {
            uint32_t boff = (uint32_t)((ne2 * 16 + bRowBase) * 528) +
                            (uint32_t)((warpN * 8 + ks) * 32) + bByte;
            uint32_t bh[4], bl[4];
            LDSM4(bh[0], bh[1], bh[2], bh[3], sb + SHI_B + boff);
            LDSM4(bl[0], bl[1], bl[2], bl[3], sb + SLO_B + boff);
            #pragma unroll
            for (int half = 0; half < 2; half++)
                #pragma unroll
                for (int mt = 0; mt < 2; mt++) {
                    uint32_t b2[2] = { bh[half * 2], bh[half * 2 + 1] };
                    MMA16816(acc2[mt][ne2 * 2 + half], ahi[mt], b2);
                }
            #pragma unroll
            for (int half = 0; half < 2; half++)
                #pragma unroll
                for (int mt = 0; mt < 2; mt++) {
                    uint32_t b2[2] = { bl[half * 2], bl[half * 2 + 1] };
                    MMA16816(acc2[mt][ne2 * 2 + half], ahi[mt], b2);
                }
            #pragma unroll
            for (int half = 0; half < 2; half++)
                #pragma unroll
                for (int mt = 0; mt < 2; mt++) {
                    uint32_t b2[2] = { bh[half * 2], bh[half * 2 + 1] };
                    MMA16816(acc2[mt][ne2 * 2 + half], alo[mt], b2);
                }
        }
    }

    // combine partials across warpN
    if (warpN == 1) {
        float* cb = (float*)(dsm + CBUF_B);
        #pragma unroll
        for (int mt = 0; mt < 2; mt++)
            #pragma unroll
            for (int nf = 0; nf < 8; nf++) {
                int r = warpM * 32 + mt * 16 + qr;
                int c = nf * 8 + qc;
                *(float2*)(cb + r * 68 + c)       = make_float2(acc2[mt][nf][0], acc2[mt][nf][1]);
                *(float2*)(cb + (r + 8) * 68 + c) = make_float2(acc2[mt][nf][2], acc2[mt][nf][3]);
            }
    }
    __syncthreads();

    if (warpN == 0) {
        const float* cb = (const float*)(dsm + CBUF_B);
        const float* sInv = (const float*)(dsm + SINV_B);
        const float* sMask = (const float*)(dsm + MASK_B);
        float* sc = (float*)(dsm + SCBUF_B);
        #pragma unroll
        for (int mt = 0; mt < 2; mt++) {
            int r0 = warpM * 32 + mt * 16 + qr, r1 = r0 + 8;
            float inv0 = sInv[r0], inv1 = sInv[r1];
            float p0[16], p1[16];
            #pragma unroll
            for (int nf = 0; nf < 8; nf++) {
                int c = nf * 8 + qc;
                float2 c0 = *(const float2*)(cb + r0 * 68 + c);
                float2 c1 = *(const float2*)(cb + r1 * 68 + c);
                bool m0 = sMask[c] == 0.f, m1 = sMask[c + 1] == 0.f;
                float a  = m0 ? -1e9f : (acc2[mt][nf][0] + c0.x) * inv0;
                float b  = m1 ? -1e9f : (acc2[mt][nf][1] + c0.y) * inv0;
                float cc = m0 ? -1e9f : (acc2[mt][nf][2] + c1.x) * inv1;
                float dd = m1 ? -1e9f : (acc2[mt][nf][3] + c1.y) * inv1;
                p0[nf * 2] = a;  p0[nf * 2 + 1] = b;
                p1[nf * 2] = cc; p1[nf * 2 + 1] = dd;
                *(float2*)(out_logits + (size_t)(tokBase + r0) * NE + c) = make_float2(a, b);
                *(float2*)(out_logits + (size_t)(tokBase + r1) * NE + c) = make_float2(cc, dd);
            }
            if (write_topk) {
                float m0 = -1e30f, m1 = -1e30f;
                #pragma unroll
                for (int j = 0; j < 16; j++) { m0 = fmaxf(m0, p0[j]); m1 = fmaxf(m1, p1[j]); }
                #pragma unroll
                for (int o = 1; o < 4; o <<= 1) {
                    m0 = fmaxf(m0, __shfl_xor_sync(0xffffffffu, m0, o));
                    m1 = fmaxf(m1, __shfl_xor_sync(0xffffffffu, m1, o));
                }
                float s0 = 0.f, s1 = 0.f;
                #pragma unroll
                for (int j = 0; j < 16; j++) {
                    p0[j] = __expf(p0[j] - m0); s0 += p0[j];
                    p1[j] = __expf(p1[j] - m1); s1 += p1[j];
                }
                #pragma unroll
                for (int o = 1; o < 4; o <<= 1) {
                    s0 += __shfl_xor_sync(0xffffffffu, s0, o);
                    s1 += __shfl_xor_sync(0xffffffffu, s1, o);
                }
                float is0 = 1.f / s0, is1 = 1.f / s1;
                #pragma unroll
                for (int nf = 0; nf < 8; nf++) {
                    int c = nf * 8 + qc;
                    *(float2*)(sc + r0 * 68 + c) =
                        make_float2(p0[nf * 2] * is0 + 1e-14f, p0[nf * 2 + 1] * is0 + 1e-14f);
                    *(float2*)(sc + r1 * 68 + c) =
                        make_float2(p1[nf * 2] * is1 + 1e-14f, p1[nf * 2 + 1] * is1 + 1e-14f);
                }
            }
        }
    }
    __syncthreads();

    if (write_topk && tid < 128) {
        const float* row = (const float*)(dsm + SCBUF_B) + tid * 68;
        float v[64];
        #pragma unroll
        for (int i = 0; i < 16; i++)
            *(float4*)(v + i * 4) = *(const float4*)(row + i * 4);
        #pragma unroll
        for (int k = 2; k <= 64; k <<= 1)
            #pragma unroll
            for (int j = k >> 1; j > 0; j >>= 1)
                #pragma unroll
                for (int i = 0; i < 64; i++) {
                    int p = i ^ j;
                    if (p > i) {
                        bool up = ((i & k) == 0);
                        float a = v[i], b = v[p];
                        bool sw = up ? (a > b) : (a < b);
                        float lo = sw ? b : a, hi = sw ? a : b;
                        v[i] = lo; v[p] = hi;
                    }
                }
        float cum = 0.f; int k = 0;
        #pragma unroll
        for (int r = 63; r >= 0; r--) { if (cum < 1.f) k++; cum += v[r]; }
        out_topk[tokBase + tid] = fminf((float)k, g_active);
    }
}

// ---------------- launch ----------------
extern "C" void kernel_launch(void* const* d_in, const int* in_sizes, int n_in,
                              void* d_out, int out_size) {
    const float* x    = (const float*)d_in[0];
    const float* W    = (const float*)d_in[1];
    const float* b    = (const float*)d_in[2];
    const float* sim  = (const float*)d_in[3];
    const float* temp = (const float*)d_in[4];
    const float* mask = (const float*)d_in[5];
    float* out = (float*)d_out;

    cudaFuncSetAttribute(fused_kernel, cudaFuncAttributeMaxDynamicSharedMemorySize, SMEM_TOTAL);

    convert_w_kernel<<<256, 256>>>(W);
    prep_kernel<<<1, 64>>>(sim, temp, mask);

    const int logits_elems = NTOK * NE;
    int write_topk = (out_size >= logits_elems + NTOK) ? 1 : 0;
    fused_kernel<<<NTOK / 128, 256, SMEM_TOTAL>>>(x, b, mask, out, out + logits_elems, write_topk);
}